// round 15
// baseline (speedup 1.0000x reference)
#include <cuda_runtime.h>
#include <cuda_bf16.h>
#include <cuda_fp16.h>
#include <stdint.h>

#define CC 256
#define C3 768
#define NPIX 4096
#define BATCH 16
#define NHEAD 8
#define APITCH 144
#define BPITCH 144
#define ATILE (256 * APITCH)     // 36864
#define BTILE (128 * BPITCH)     // 18432
#define STAGE (ATILE + BTILE)    // 55296
#define NSTAGE 3
#define DYN_SMEM (NSTAGE * STAGE) // 165888 -> 1 CTA/SM, 16 warps

// attention smem per head: q,k,v each 32 rows x 144B
#define AH_T 4608
#define AH_BYTES (3 * AH_T)      // 13824
#define ATTN_SMEM (4 * AH_BYTES) // 55296

// ---------------- scratch -----------------------------------------------
__device__ __align__(16) __half g_qkv[(size_t)BATCH * C3 * NPIX];
__device__ __align__(16) __half g_xs [(size_t)BATCH * NPIX * CC];
__device__ __align__(16) __half g_as [(size_t)BATCH * NPIX * CC];
__device__ __align__(16) __half g_wqs[(size_t)C3 * CC];
__device__ __align__(16) __half g_wps[(size_t)CC * CC];

// ---------------- helpers -------------------------------------------------
__device__ __forceinline__ uint32_t smem_u32(const void* p) {
    uint32_t a;
    asm("{ .reg .u64 t; cvta.to.shared.u64 t, %1; cvt.u32.u64 %0, t; }" : "=r"(a) : "l"(p));
    return a;
}
__device__ __forceinline__ void cp16(uint32_t d, const void* s) {
    asm volatile("cp.async.cg.shared.global [%0], [%1], 16;" :: "r"(d), "l"(s) : "memory");
}
__device__ __forceinline__ void cp_commit() {
    asm volatile("cp.async.commit_group;" ::: "memory");
}
template <int N> __device__ __forceinline__ void cp_wait() {
    asm volatile("cp.async.wait_group %0;" :: "n"(N) : "memory");
}
__device__ __forceinline__ void ldsm4(uint32_t& r0, uint32_t& r1, uint32_t& r2, uint32_t& r3,
                                      uint32_t addr) {
    asm volatile("ldmatrix.sync.aligned.m8n8.x4.shared.b16 {%0,%1,%2,%3}, [%4];"
                 : "=r"(r0), "=r"(r1), "=r"(r2), "=r"(r3) : "r"(addr));
}
__device__ __forceinline__ void ldsm4t(uint32_t& r0, uint32_t& r1, uint32_t& r2, uint32_t& r3,
                                       uint32_t addr) {
    asm volatile("ldmatrix.sync.aligned.m8n8.x4.trans.shared.b16 {%0,%1,%2,%3}, [%4];"
                 : "=r"(r0), "=r"(r1), "=r"(r2), "=r"(r3) : "r"(addr));
}
__device__ __forceinline__ void mmah(float* d,
                                     uint32_t a0, uint32_t a1, uint32_t a2, uint32_t a3,
                                     uint32_t b0, uint32_t b1) {
    asm volatile(
        "mma.sync.aligned.m16n8k16.row.col.f32.f16.f16.f32 "
        "{%0,%1,%2,%3}, {%4,%5,%6,%7}, {%8,%9}, {%0,%1,%2,%3};"
        : "+f"(d[0]), "+f"(d[1]), "+f"(d[2]), "+f"(d[3])
        : "r"(a0), "r"(a1), "r"(a2), "r"(a3), "r"(b0), "r"(b1));
}
__device__ __forceinline__ uint32_t packh2(float a, float b) {
    __half2 t = __floats2half2_rn(a, b);
    return *(uint32_t*)&t;
}

// ---------------------------------------------------------------------------
// Single-fp16 GEMM, 256M x 128N CTA tile, 512 thr (16 warps, 4m x 4n of 64x32),
// 3-stage cp.async. ntiles N-tiles per CTA with a CONTINUOUS pipeline: the
// epilogue of tile t overlaps the prefetch of tile t+1 (no drain).
// One commit every iteration (incl. empty) keeps wait_group math exact.
// grid = (32/ntiles, Mtot/256, 16)
// ---------------------------------------------------------------------------
__global__ __launch_bounds__(512, 1)
void gemm_fp16(const __half* __restrict__ A,
               const __half* __restrict__ Bm,
               void* __restrict__ Dv, int Mtot,
               const int* __restrict__ shift_ptr, int permute, int out_half,
               int ntiles)
{
    extern __shared__ __align__(16) char dsm[];

    const int tid = threadIdx.x;
    const int wid = tid >> 5;
    const int lid = tid & 31;
    const int bn0 = blockIdx.x * ntiles, bm = blockIdx.y, b = blockIdx.z;

    const int warp_m = wid & 3;   // 4 x 64 rows
    const int warp_n = wid >> 2;  // 4 x 32 cols
    const uint32_t gq = lid >> 2, tq = lid & 3;

    const uint32_t sbase = smem_u32(dsm);

    // A fill: row = tid>>1 (0..255), 64B half -> 4 cp16 per chunk
    const int ra = tid >> 1, ha = tid & 1;
    // B fill: row = tid>>2 (0..127), 32B quarter -> 2 cp16 per chunk
    const int rb = tid >> 2, qb = tid & 3;
    const char* Ag = (const char*)A + (size_t)(bm * 256 + ra) * 512 + (size_t)ha * 64;
    const char* Bg = (const char*)Bm
        + ((size_t)b * NPIX + (size_t)bn0 * 128 + (size_t)rb) * 512 + (size_t)qb * 32;
    const uint32_t srowA = (uint32_t)ra * APITCH + (uint32_t)ha * 64;
    const uint32_t srowB = (uint32_t)rb * BPITCH + (uint32_t)qb * 32;

    const int ncc = ntiles * 4;   // total virtual chunks

    auto fill = [&](int cc) {
        const int s = cc % NSTAGE;
        const int tt = cc >> 2, kc = cc & 3;
        const uint32_t sa = sbase + (uint32_t)s * STAGE;
        const uint32_t sb = sa + ATILE;
        const char* ag = Ag + (size_t)kc * 128;
        const char* bg = Bg + (size_t)tt * 65536 + (size_t)kc * 128; // 128 rows * 512B
#pragma unroll
        for (int j = 0; j < 4; j++) cp16(sa + srowA + j * 16, ag + j * 16);
#pragma unroll
        for (int j = 0; j < 2; j++) cp16(sb + srowB + j * 16, bg + j * 16);
        cp_commit();
    };

    fill(0);
    fill(1);
    fill(2);

    const uint32_t lr = lid & 15, lh = lid >> 4;
    const uint32_t pAr = (uint32_t)(warp_m * 64 + lr) * APITCH + lh * 16u;
    const uint32_t pBr = (uint32_t)(warp_n * 32 + lr) * BPITCH + lh * 16u;

    const int sft = (permute && (*shift_ptr != 0)) ? 4 : 0;
    const int row_base = bm * 256 + warp_m * 64 + (int)gq;

#pragma unroll 1
    for (int t = 0; t < ntiles; t++) {
        float acc[4][4][4];
#pragma unroll
        for (int mi = 0; mi < 4; mi++)
#pragma unroll
            for (int ni = 0; ni < 4; ni++)
#pragma unroll
                for (int e = 0; e < 4; e++) acc[mi][ni][e] = 0.0f;

#pragma unroll
        for (int c = 0; c < 4; c++) {
            const int cc = t * 4 + c;
            cp_wait<NSTAGE - 1>();
            __syncthreads();
            const uint32_t so = sbase + (uint32_t)(cc % NSTAGE) * STAGE;
            const uint32_t pA = so + pAr;
            const uint32_t pB = so + ATILE + pBr;

#pragma unroll
            for (int ks = 0; ks < 4; ks++) {
                const uint32_t ko = 32u * ks;
                uint32_t bfr[4][2];
#pragma unroll
                for (int j = 0; j < 2; j++) {
                    uint32_t r0, r1, r2, r3;
                    ldsm4(r0, r1, r2, r3, pB + (uint32_t)j * (16 * BPITCH) + ko);
                    bfr[2 * j][0] = r0;     bfr[2 * j][1] = r2;
                    bfr[2 * j + 1][0] = r1; bfr[2 * j + 1][1] = r3;
                }
                uint32_t af[4][4];
#pragma unroll
                for (int mi = 0; mi < 4; mi++)
                    ldsm4(af[mi][0], af[mi][1], af[mi][2], af[mi][3],
                          pA + (uint32_t)mi * (16 * APITCH) + ko);
#pragma unroll
                for (int mi = 0; mi < 4; mi++)
#pragma unroll
                    for (int ni = 0; ni < 4; ni++)
                        mmah(acc[mi][ni], af[mi][0], af[mi][1], af[mi][2], af[mi][3],
                             bfr[ni][0], bfr[ni][1]);
            }
            __syncthreads();
            if (cc + NSTAGE < ncc) fill(cc + NSTAGE);
            else                   cp_commit();   // empty group: keep wait math exact
        }

        // ---- epilogue for tile t (register-only; pipeline keeps streaming) ----
        const int bn = bn0 + t;
        const int col_base = bn * 128 + warp_n * 32 + 2 * (int)tq;
        if (out_half) {
            __half* Dh = (__half*)Dv + (size_t)b * Mtot * NPIX;
#pragma unroll
            for (int mi = 0; mi < 4; mi++) {
                const int r0 = row_base + mi * 16;
#pragma unroll
                for (int ni = 0; ni < 4; ni++) {
                    const int cl = col_base + ni * 8;
                    *(uint32_t*)(Dh + (size_t)r0 * NPIX + cl) =
                        packh2(acc[mi][ni][0], acc[mi][ni][1]);
                    *(uint32_t*)(Dh + (size_t)(r0 + 8) * NPIX + cl) =
                        packh2(acc[mi][ni][2], acc[mi][ni][3]);
                }
            }
        } else {
            float* Db = (float*)Dv + (size_t)b * Mtot * NPIX;
#pragma unroll
            for (int mi = 0; mi < 4; mi++) {
                const int r0 = row_base + mi * 16;
#pragma unroll
                for (int ni = 0; ni < 4; ni++) {
                    int cl = col_base + ni * 8;
                    int col;
                    if (permute) {
                        const int win = cl >> 6, tok = cl & 63;
                        const int gh = (((win >> 3) << 3) + (tok >> 3) + sft) & 63;
                        const int gw = (((win & 7) << 3) + (tok & 7) + sft) & 63;
                        col = gh * 64 + gw;   // gw, sft even: float2 never wraps
                    } else {
                        col = cl;
                    }
                    *(float2*)(Db + (size_t)r0 * NPIX + col) =
                        make_float2(acc[mi][ni][0], acc[mi][ni][1]);
                    *(float2*)(Db + (size_t)(r0 + 8) * NPIX + col) =
                        make_float2(acc[mi][ni][2], acc[mi][ni][3]);
                }
            }
        }
    }
}

// ---------------------------------------------------------------------------
// Merged weight convert: w_qkv (Q rows scaled by 1/sqrt(32)) then w_proj.
// grid = 1024 blocks x 256 thr
// ---------------------------------------------------------------------------
__global__ void convert_w2(const float* __restrict__ Wq, const float* __restrict__ Wp,
                           __half* __restrict__ Wqs, __half* __restrict__ Wps)
{
    int id = blockIdx.x * 256 + threadIdx.x;
    if (id < C3 * 256) {
        float v = Wq[id];
        if ((id >> 8) < CC) v *= 0.17677669529663688f;   // 1/sqrt(32) into Q rows
        Wqs[id] = __float2half(v);
    } else {
        int j = id - C3 * 256;   // < CC*256
        Wps[j] = __float2half(Wp[j]);
    }
}

__global__ __launch_bounds__(256) void convert_x(const float* __restrict__ X,
                                                 __half* __restrict__ Xs,
                                                 const int* __restrict__ shift_ptr)
{
    __shared__ float s[32][33];
    const int p0 = blockIdx.x * 32, k0 = blockIdx.y * 32, b = blockIdx.z;
    const int tx = threadIdx.x & 31, ty = threadIdx.x >> 5;
    const int sft = (*shift_ptr != 0) ? 4 : 0;
    const float* xb = X + ((size_t)b * CC + k0) * NPIX + p0;
#pragma unroll
    for (int kk = ty; kk < 32; kk += 8) s[kk][tx] = xb[(size_t)kk * NPIX + tx];
    __syncthreads();
#pragma unroll
    for (int pp = ty; pp < 32; pp += 8) {
        const int p = p0 + pp;
        const int gh = p >> 6, gw = p & 63;
        const int hp = (gh - sft) & 63, wp = (gw - sft) & 63;
        const int pprime = (((hp >> 3) << 3) + (wp >> 3)) * 64 + ((hp & 7) << 3) + (wp & 7);
        Xs[((size_t)b * NPIX + pprime) * CC + k0 + tx] = __float2half(s[tx][pp]);
    }
}

// ---------------------------------------------------------------------------
// HMMA windowed attention: all-fp16 in via cp.async, single-V PV.
// One warp = (head, window). grid = (2, 64, 16), block 128.
// ---------------------------------------------------------------------------
__global__ __launch_bounds__(128) void attn_kernel(
    const __half* __restrict__ qkv, __half* __restrict__ attns)
{
    extern __shared__ __align__(16) char smema[];
    const int tid = threadIdx.x;
    const int lid = tid & 31, wid = tid >> 5;
    const int head = blockIdx.x * 4 + wid;
    const int win = blockIdx.y, b = blockIdx.z;

    const uint32_t hb = smem_u32(smema) + (uint32_t)wid * AH_BYTES;
    const uint32_t qsm = hb, ksm = hb + AH_T, vsm = hb + 2 * AH_T;

    {
        const size_t base = (size_t)b * C3 * NPIX + (size_t)(head * 32 + lid) * NPIX
                          + (size_t)win * 64;
        const char* gq = (const char*)(qkv + base);
        const char* gk = (const char*)(qkv + base + (size_t)CC * NPIX);
        const char* gv = (const char*)(qkv + base + (size_t)(2 * CC) * NPIX);
        const uint32_t dr = (uint32_t)lid * 144u;
#pragma unroll
        for (int j = 0; j < 8; j++) {
            cp16(qsm + dr + j * 16, gq + j * 16);
            cp16(ksm + dr + j * 16, gk + j * 16);
            cp16(vsm + dr + j * 16, gv + j * 16);
        }
        cp_commit();
        cp_wait<0>();
        __syncwarp();
    }

    const uint32_t tr  = (uint32_t)((lid & 7) + ((lid & 16) >> 1));
    const uint32_t tcb = (uint32_t)(lid & 8) * 2u;
    const uint32_t vr  = (uint32_t)(lid & 15);
    const uint32_t vh16 = (uint32_t)(lid >> 4) * 16u;

    float O[4][4][4];
    float rs[4][2];
#pragma unroll
    for (int mi = 0; mi < 4; mi++) {
        rs[mi][0] = 0.0f; rs[mi][1] = 0.0f;
#pragma unroll
        for (int nt = 0; nt < 4; nt++)
#pragma unroll
            for (int e = 0; e < 4; e++) O[mi][nt][e] = 0.0f;
    }

#pragma unroll 1
    for (int half = 0; half < 2; half++) {
        float S[4][4][4];
#pragma unroll
        for (int mi = 0; mi < 4; mi++)
#pragma unroll
            for (int nj = 0; nj < 4; nj++)
#pragma unroll
                for (int e = 0; e < 4; e++) S[mi][nj][e] = 0.0f;

#pragma unroll
        for (int kk = 0; kk < 2; kk++) {
            uint32_t af[4][4];
#pragma unroll
            for (int mi = 0; mi < 4; mi++)
                ldsm4t(af[mi][0], af[mi][1], af[mi][2], af[mi][3],
                       qsm + ((uint32_t)kk * 16u + tr) * 144u
                           + (uint32_t)(mi * 16) * 2u + tcb);
            uint32_t bf2[4][2];
#pragma unroll
            for (int jj = 0; jj < 2; jj++) {
                uint32_t r0, r1, r2, r3;
                ldsm4t(r0, r1, r2, r3,
                       ksm + ((uint32_t)kk * 16u + tr) * 144u
                           + (uint32_t)(half * 32 + jj * 16) * 2u + tcb);
                bf2[2 * jj][0] = r0;     bf2[2 * jj][1] = r2;
                bf2[2 * jj + 1][0] = r1; bf2[2 * jj + 1][1] = r3;
            }
#pragma unroll
            for (int mi = 0; mi < 4; mi++)
#pragma unroll
                for (int nj = 0; nj < 4; nj++)
                    mmah(S[mi][nj], af[mi][0], af[mi][1], af[mi][2], af[mi][3],
                         bf2[nj][0], bf2[nj][1]);
        }

#pragma unroll
        for (int mi = 0; mi < 4; mi++)
#pragma unroll
            for (int nj = 0; nj < 4; nj++) {
                S[mi][nj][0] = __expf(S[mi][nj][0]);
                S[mi][nj][1] = __expf(S[mi][nj][1]);
                S[mi][nj][2] = __expf(S[mi][nj][2]);
                S[mi][nj][3] = __expf(S[mi][nj][3]);
                rs[mi][0] += S[mi][nj][0] + S[mi][nj][1];
                rs[mi][1] += S[mi][nj][2] + S[mi][nj][3];
            }

#pragma unroll
        for (int kk = 0; kk < 2; kk++) {
            uint32_t bv[4][2];
            const uint32_t kcb = (uint32_t)(half * 64 + kk * 32) + vh16;
#pragma unroll
            for (int nn = 0; nn < 2; nn++) {
                uint32_t r0, r1, r2, r3;
                ldsm4(r0, r1, r2, r3, vsm + ((uint32_t)(nn * 16) + vr) * 144u + kcb);
                bv[2 * nn][0] = r0;     bv[2 * nn][1] = r2;
                bv[2 * nn + 1][0] = r1; bv[2 * nn + 1][1] = r3;
            }
#pragma unroll
            for (int mi = 0; mi < 4; mi++) {
                uint32_t pa0 = packh2(S[mi][2 * kk][0],     S[mi][2 * kk][1]);
                uint32_t pa1 = packh2(S[mi][2 * kk][2],     S[mi][2 * kk][3]);
                uint32_t pa2 = packh2(S[mi][2 * kk + 1][0], S[mi][2 * kk + 1][1]);
                uint32_t pa3 = packh2(S[mi][2 * kk + 1][2], S[mi][2 * kk + 1][3]);
#pragma unroll
                for (int nt = 0; nt < 4; nt++)
                    mmah(O[mi][nt], pa0, pa1, pa2, pa3, bv[nt][0], bv[nt][1]);
            }
        }
    }

#pragma unroll
    for (int mi = 0; mi < 4; mi++)
#pragma unroll
        for (int r = 0; r < 2; r++) {
            rs[mi][r] += __shfl_xor_sync(0xFFFFFFFFu, rs[mi][r], 1);
            rs[mi][r] += __shfl_xor_sync(0xFFFFFFFFu, rs[mi][r], 2);
        }

    const int tq = lid & 3, g = lid >> 2;
    const int c0 = head * 32;
#pragma unroll
    for (int mi = 0; mi < 4; mi++) {
        const float i0 = 1.0f / rs[mi][0];
        const float i1 = 1.0f / rs[mi][1];
        const int tok0 = win * 64 + mi * 16 + g;
        __half* r0p = attns + ((size_t)b * NPIX + tok0) * CC + c0;
        __half* r8p = r0p + 8 * CC;
#pragma unroll
        for (int nt = 0; nt < 4; nt++) {
            const int d = nt * 8 + 2 * tq;
            *(uint32_t*)(r0p + d) = packh2(O[mi][nt][0] * i0, O[mi][nt][1] * i0);
            *(uint32_t*)(r8p + d) = packh2(O[mi][nt][2] * i1, O[mi][nt][3] * i1);
        }
    }
}

// ---------------------------------------------------------------------------
extern "C" void kernel_launch(void* const* d_in, const int* in_sizes, int n_in,
                              void* d_out, int out_size)
{
    (void)in_sizes; (void)n_in; (void)out_size;
    const float* x      = (const float*)d_in[0];
    const float* w_qkv  = (const float*)d_in[1];
    const float* w_proj = (const float*)d_in[2];
    const int*   shift  = (const int*)d_in[3];

    __half *qkv, *xs, *as, *wqs, *wps;
    cudaGetSymbolAddress((void**)&qkv, g_qkv);
    cudaGetSymbolAddress((void**)&xs,  g_xs);
    cudaGetSymbolAddress((void**)&as,  g_as);
    cudaGetSymbolAddress((void**)&wqs, g_wqs);
    cudaGetSymbolAddress((void**)&wps, g_wps);

    cudaFuncSetAttribute(gemm_fp16, cudaFuncAttributeMaxDynamicSharedMemorySize, DYN_SMEM);
    cudaFuncSetAttribute(attn_kernel, cudaFuncAttributeMaxDynamicSharedMemorySize, ATTN_SMEM);

    convert_w2<<<1024, 256>>>(w_qkv, w_proj, wqs, wps);
    convert_x<<<dim3(128, 8, 16), 256>>>(x, xs, shift);

    // K1: qkv = W @ X, fp16 out (permuted space), 2 N-tiles per CTA
    gemm_fp16<<<dim3(16, 3, 16), 512, DYN_SMEM>>>(wqs, xs, qkv, C3, shift, 0, 1, 2);

    attn_kernel<<<dim3(2, 64, 16), 128, ATTN_SMEM>>>(qkv, as);

    // K3: out = W_proj @ attn, fp32 out, un-permute epilogue, 1 N-tile
    gemm_fp16<<<dim3(32, 1, 16), 512, DYN_SMEM>>>(wps, as, d_out, CC, shift, 1, 0, 1);
}

// round 16
// speedup vs baseline: 1.0677x; 1.0677x over previous
#include <cuda_runtime.h>
#include <cuda_bf16.h>
#include <cuda_fp16.h>
#include <stdint.h>

#define CC 256
#define C3 768
#define NPIX 4096
#define BATCH 16
#define NHEAD 8
#define NCH 4                 // 4 k-chunks of 64
#define PITCH 144             // 128B chunk-row + 16B pad
#define TILE (128 * PITCH)       // 18432 per operand
#define STAGE (2 * TILE)         // 36864
#define NSTAGE 3
#define DYN_SMEM (NSTAGE * STAGE) // 110592 -> 2 CTAs/SM

// attention smem per head: q,k,v each 32 rows x 144B
#define AH_T 4608
#define AH_BYTES (3 * AH_T)      // 13824
#define ATTN_SMEM (4 * AH_BYTES) // 55296 (4 heads per block)

// ---------------- scratch -----------------------------------------------
__device__ __align__(16) __half g_qkv[(size_t)BATCH * C3 * NPIX];
__device__ __align__(16) __half g_xs [(size_t)BATCH * NPIX * CC];
__device__ __align__(16) __half g_as [(size_t)BATCH * NPIX * CC];
__device__ __align__(16) __half g_wqs[(size_t)C3 * CC];
__device__ __align__(16) __half g_wps[(size_t)CC * CC];

// ---------------- helpers -------------------------------------------------
__device__ __forceinline__ uint32_t smem_u32(const void* p) {
    uint32_t a;
    asm("{ .reg .u64 t; cvta.to.shared.u64 t, %1; cvt.u32.u64 %0, t; }" : "=r"(a) : "l"(p));
    return a;
}
__device__ __forceinline__ void cp16(uint32_t d, const void* s) {
    asm volatile("cp.async.cg.shared.global [%0], [%1], 16;" :: "r"(d), "l"(s) : "memory");
}
__device__ __forceinline__ void cp_commit() {
    asm volatile("cp.async.commit_group;" ::: "memory");
}
template <int N> __device__ __forceinline__ void cp_wait() {
    asm volatile("cp.async.wait_group %0;" :: "n"(N) : "memory");
}
__device__ __forceinline__ void ldsm4(uint32_t& r0, uint32_t& r1, uint32_t& r2, uint32_t& r3,
                                      uint32_t addr) {
    asm volatile("ldmatrix.sync.aligned.m8n8.x4.shared.b16 {%0,%1,%2,%3}, [%4];"
                 : "=r"(r0), "=r"(r1), "=r"(r2), "=r"(r3) : "r"(addr));
}
__device__ __forceinline__ void ldsm4t(uint32_t& r0, uint32_t& r1, uint32_t& r2, uint32_t& r3,
                                       uint32_t addr) {
    asm volatile("ldmatrix.sync.aligned.m8n8.x4.trans.shared.b16 {%0,%1,%2,%3}, [%4];"
                 : "=r"(r0), "=r"(r1), "=r"(r2), "=r"(r3) : "r"(addr));
}
__device__ __forceinline__ void mmah(float* d,
                                     uint32_t a0, uint32_t a1, uint32_t a2, uint32_t a3,
                                     uint32_t b0, uint32_t b1) {
    asm volatile(
        "mma.sync.aligned.m16n8k16.row.col.f32.f16.f16.f32 "
        "{%0,%1,%2,%3}, {%4,%5,%6,%7}, {%8,%9}, {%0,%1,%2,%3};"
        : "+f"(d[0]), "+f"(d[1]), "+f"(d[2]), "+f"(d[3])
        : "r"(a0), "r"(a1), "r"(a2), "r"(a3), "r"(b0), "r"(b1));
}
__device__ __forceinline__ uint32_t packh2(float a, float b) {
    __half2 t = __floats2half2_rn(a, b);
    return *(uint32_t*)&t;
}

// ---------------------------------------------------------------------------
// Single-fp16 GEMM (round-14 exact): 128M x 128N CTA, 256 thr (2m x 4n of
// 64x32), 3-stage cp.async, 2 CTAs/SM, commit-every-iteration race fix.
// grid = (32, Mtot/128, 16)
// ---------------------------------------------------------------------------
__global__ __launch_bounds__(256, 2)
void gemm_fp16(const __half* __restrict__ A,
               const __half* __restrict__ Bm,
               void* __restrict__ Dv, int Mtot,
               const int* __restrict__ shift_ptr, int permute, int out_half)
{
    extern __shared__ __align__(16) char dsm[];

    const int tid = threadIdx.x;
    const int wid = tid >> 5;
    const int lid = tid & 31;
    const int bn = blockIdx.x, bm = blockIdx.y, b = blockIdx.z;

    const int warp_m = wid & 1;
    const int warp_n = wid >> 1;
    const uint32_t gq = lid >> 2, tq = lid & 3;

    const uint32_t sbase = smem_u32(dsm);

    const int r = tid >> 1, h = tid & 1;
    const char* Ag = (const char*)A + (size_t)(bm * 128 + r) * 512 + (size_t)h * 64;
    const char* Bg = (const char*)Bm
        + ((size_t)b * NPIX + (size_t)bn * 128 + (size_t)r) * 512 + (size_t)h * 64;
    const uint32_t srow = (uint32_t)r * PITCH + (uint32_t)h * 64;

    auto fill = [&](int c, int s) {
        const uint32_t sa = sbase + (uint32_t)s * STAGE + srow;
        const uint32_t sb = sa + TILE;
        const char* ag = Ag + (size_t)c * 128;
        const char* bg = Bg + (size_t)c * 128;
#pragma unroll
        for (int j = 0; j < 4; j++) cp16(sa + j * 16, ag + j * 16);
#pragma unroll
        for (int j = 0; j < 4; j++) cp16(sb + j * 16, bg + j * 16);
        cp_commit();
    };

    fill(0, 0);
    fill(1, 1);
    fill(2, 2);

    float acc[4][4][4];
#pragma unroll
    for (int mi = 0; mi < 4; mi++)
#pragma unroll
        for (int ni = 0; ni < 4; ni++)
#pragma unroll
            for (int e = 0; e < 4; e++) acc[mi][ni][e] = 0.0f;

    const uint32_t lr = lid & 15, lh = lid >> 4;
    const uint32_t pAr = (uint32_t)(warp_m * 64 + lr) * PITCH + lh * 16u;
    const uint32_t pBr = (uint32_t)(warp_n * 32 + lr) * PITCH + lh * 16u;

    for (int c = 0; c < NCH; c++) {
        cp_wait<NSTAGE - 1>();
        __syncthreads();
        const uint32_t so = sbase + (uint32_t)(c % NSTAGE) * STAGE;
        const uint32_t pA = so + pAr;
        const uint32_t pB = so + TILE + pBr;

#pragma unroll
        for (int ks = 0; ks < 4; ks++) {
            const uint32_t ko = 32u * ks;
            uint32_t bfr[4][2];
#pragma unroll
            for (int j = 0; j < 2; j++) {
                uint32_t r0, r1, r2, r3;
                ldsm4(r0, r1, r2, r3, pB + (uint32_t)j * (16 * PITCH) + ko);
                bfr[2 * j][0] = r0;     bfr[2 * j][1] = r2;
                bfr[2 * j + 1][0] = r1; bfr[2 * j + 1][1] = r3;
            }
            uint32_t af[4][4];
#pragma unroll
            for (int mi = 0; mi < 4; mi++)
                ldsm4(af[mi][0], af[mi][1], af[mi][2], af[mi][3],
                      pA + (uint32_t)mi * (16 * PITCH) + ko);
#pragma unroll
            for (int mi = 0; mi < 4; mi++)
#pragma unroll
                for (int ni = 0; ni < 4; ni++)
                    mmah(acc[mi][ni], af[mi][0], af[mi][1], af[mi][2], af[mi][3],
                         bfr[ni][0], bfr[ni][1]);
        }
        __syncthreads();
        if (c + NSTAGE < NCH) fill(c + NSTAGE, c % NSTAGE);
        else                  cp_commit();     // empty group: keep wait math exact
    }

    const int row_base = bm * 128 + warp_m * 64 + (int)gq;
    const int col_base = bn * 128 + warp_n * 32 + 2 * (int)tq;

    if (out_half) {
        __half* Dh = (__half*)Dv + (size_t)b * Mtot * NPIX;
#pragma unroll
        for (int mi = 0; mi < 4; mi++) {
            const int r0 = row_base + mi * 16;
#pragma unroll
            for (int ni = 0; ni < 4; ni++) {
                const int cl = col_base + ni * 8;
                *(uint32_t*)(Dh + (size_t)r0 * NPIX + cl) =
                    packh2(acc[mi][ni][0], acc[mi][ni][1]);
                *(uint32_t*)(Dh + (size_t)(r0 + 8) * NPIX + cl) =
                    packh2(acc[mi][ni][2], acc[mi][ni][3]);
            }
        }
    } else {
        const int sft = (permute && (*shift_ptr != 0)) ? 4 : 0;
        float* Db = (float*)Dv + (size_t)b * Mtot * NPIX;
#pragma unroll
        for (int mi = 0; mi < 4; mi++) {
            const int r0 = row_base + mi * 16;
#pragma unroll
            for (int ni = 0; ni < 4; ni++) {
                int cl = col_base + ni * 8;
                int col;
                if (permute) {
                    const int win = cl >> 6, tok = cl & 63;
                    const int gh = (((win >> 3) << 3) + (tok >> 3) + sft) & 63;
                    const int gw = (((win & 7) << 3) + (tok & 7) + sft) & 63;
                    col = gh * 64 + gw;
                } else {
                    col = cl;
                }
                *(float2*)(Db + (size_t)r0 * NPIX + col) =
                    make_float2(acc[mi][ni][0], acc[mi][ni][1]);
                *(float2*)(Db + (size_t)(r0 + 8) * NPIX + col) =
                    make_float2(acc[mi][ni][2], acc[mi][ni][3]);
            }
        }
    }
}

// ---------------------------------------------------------------------------
// Merged weight convert: w_qkv (Q rows scaled) then w_proj. 1024 x 256.
// ---------------------------------------------------------------------------
__global__ void convert_w2(const float* __restrict__ Wq, const float* __restrict__ Wp,
                           __half* __restrict__ Wqs, __half* __restrict__ Wps)
{
    int id = blockIdx.x * 256 + threadIdx.x;
    if (id < C3 * 256) {
        float v = Wq[id];
        if ((id >> 8) < CC) v *= 0.17677669529663688f;   // 1/sqrt(32) into Q rows
        Wqs[id] = __float2half(v);
    } else {
        int j = id - C3 * 256;
        Wps[j] = __float2half(Wp[j]);
    }
}

__global__ __launch_bounds__(256) void convert_x(const float* __restrict__ X,
                                                 __half* __restrict__ Xs,
                                                 const int* __restrict__ shift_ptr)
{
    __shared__ float s[32][33];
    const int p0 = blockIdx.x * 32, k0 = blockIdx.y * 32, b = blockIdx.z;
    const int tx = threadIdx.x & 31, ty = threadIdx.x >> 5;
    const int sft = (*shift_ptr != 0) ? 4 : 0;
    const float* xb = X + ((size_t)b * CC + k0) * NPIX + p0;
#pragma unroll
    for (int kk = ty; kk < 32; kk += 8) s[kk][tx] = xb[(size_t)kk * NPIX + tx];
    __syncthreads();
#pragma unroll
    for (int pp = ty; pp < 32; pp += 8) {
        const int p = p0 + pp;
        const int gh = p >> 6, gw = p & 63;
        const int hp = (gh - sft) & 63, wp = (gw - sft) & 63;
        const int pprime = (((hp >> 3) << 3) + (wp >> 3)) * 64 + ((hp & 7) << 3) + (wp & 7);
        Xs[((size_t)b * NPIX + pprime) * CC + k0 + tx] = __float2half(s[tx][pp]);
    }
}

// ---------------------------------------------------------------------------
// HMMA windowed attention v2: 2 warps per (head, window); each warp owns 32
// query tokens (halved S/O register arrays -> ~2x occupancy). Block = 256 thr
// = 4 heads x 2 q-halves; warp pair shares the head's smem K/V.
// grid = (2, 64, 16), block 256.
// ---------------------------------------------------------------------------
__global__ __launch_bounds__(256) void attn_kernel(
    const __half* __restrict__ qkv, __half* __restrict__ attns)
{
    extern __shared__ __align__(16) char smema[];
    const int tid = threadIdx.x;
    const int lid = tid & 31, wid = tid >> 5;
    const int hslot = wid >> 1;          // 0..3
    const int mhalf = wid & 1;           // q-token half
    const int head = blockIdx.x * 4 + hslot;
    const int win = blockIdx.y, b = blockIdx.z;

    const uint32_t hb = smem_u32(smema) + (uint32_t)hslot * AH_BYTES;
    const uint32_t qsm = hb, ksm = hb + AH_T, vsm = hb + 2 * AH_T;

    // ---- loads: even warp q+k, odd warp v (one 128B row per lane) ----
    {
        const size_t base = (size_t)b * C3 * NPIX + (size_t)(head * 32 + lid) * NPIX
                          + (size_t)win * 64;
        const uint32_t dr = (uint32_t)lid * 144u;
        if (mhalf == 0) {
            const char* gq = (const char*)(qkv + base);
            const char* gk = (const char*)(qkv + base + (size_t)CC * NPIX);
#pragma unroll
            for (int j = 0; j < 8; j++) {
                cp16(qsm + dr + j * 16, gq + j * 16);
                cp16(ksm + dr + j * 16, gk + j * 16);
            }
        } else {
            const char* gv = (const char*)(qkv + base + (size_t)(2 * CC) * NPIX);
#pragma unroll
            for (int j = 0; j < 8; j++)
                cp16(vsm + dr + j * 16, gv + j * 16);
        }
        cp_commit();
        cp_wait<0>();
        __syncthreads();
    }

    const uint32_t tr  = (uint32_t)((lid & 7) + ((lid & 16) >> 1));
    const uint32_t tcb = (uint32_t)(lid & 8) * 2u;
    const uint32_t vr  = (uint32_t)(lid & 15);
    const uint32_t vh16 = (uint32_t)(lid >> 4) * 16u;
    const uint32_t mq = (uint32_t)(mhalf * 64);   // byte offset of this warp's 32 q tokens

    float O[2][4][4];
    float rs[2][2];
#pragma unroll
    for (int mi = 0; mi < 2; mi++) {
        rs[mi][0] = 0.0f; rs[mi][1] = 0.0f;
#pragma unroll
        for (int nt = 0; nt < 4; nt++)
#pragma unroll
            for (int e = 0; e < 4; e++) O[mi][nt][e] = 0.0f;
    }

#pragma unroll 1
    for (int half = 0; half < 2; half++) {     // key halves
        float S[2][4][4];
#pragma unroll
        for (int mi = 0; mi < 2; mi++)
#pragma unroll
            for (int nj = 0; nj < 4; nj++)
#pragma unroll
                for (int e = 0; e < 4; e++) S[mi][nj][e] = 0.0f;

        // ---- S = Q.K^T ----
#pragma unroll
        for (int kk = 0; kk < 2; kk++) {
            uint32_t af[2][4];
#pragma unroll
            for (int mi = 0; mi < 2; mi++)
                ldsm4t(af[mi][0], af[mi][1], af[mi][2], af[mi][3],
                       qsm + ((uint32_t)kk * 16u + tr) * 144u
                           + mq + (uint32_t)(mi * 32) + tcb);
            uint32_t bf2[4][2];
#pragma unroll
            for (int jj = 0; jj < 2; jj++) {
                uint32_t r0, r1, r2, r3;
                ldsm4t(r0, r1, r2, r3,
                       ksm + ((uint32_t)kk * 16u + tr) * 144u
                           + (uint32_t)(half * 64 + jj * 32) + tcb);
                bf2[2 * jj][0] = r0;     bf2[2 * jj][1] = r2;
                bf2[2 * jj + 1][0] = r1; bf2[2 * jj + 1][1] = r3;
            }
#pragma unroll
            for (int mi = 0; mi < 2; mi++)
#pragma unroll
                for (int nj = 0; nj < 4; nj++)
                    mmah(S[mi][nj], af[mi][0], af[mi][1], af[mi][2], af[mi][3],
                         bf2[nj][0], bf2[nj][1]);
        }

        // ---- exp + partial row sums ----
#pragma unroll
        for (int mi = 0; mi < 2; mi++)
#pragma unroll
            for (int nj = 0; nj < 4; nj++) {
                S[mi][nj][0] = __expf(S[mi][nj][0]);
                S[mi][nj][1] = __expf(S[mi][nj][1]);
                S[mi][nj][2] = __expf(S[mi][nj][2]);
                S[mi][nj][3] = __expf(S[mi][nj][3]);
                rs[mi][0] += S[mi][nj][0] + S[mi][nj][1];
                rs[mi][1] += S[mi][nj][2] + S[mi][nj][3];
            }

        // ---- O += P.V ----
#pragma unroll
        for (int kk = 0; kk < 2; kk++) {
            uint32_t bv[4][2];
            const uint32_t kcb = (uint32_t)(half * 64 + kk * 32) + vh16;
#pragma unroll
            for (int nn = 0; nn < 2; nn++) {
                uint32_t r0, r1, r2, r3;
                ldsm4(r0, r1, r2, r3, vsm + ((uint32_t)(nn * 16) + vr) * 144u + kcb);
                bv[2 * nn][0] = r0;     bv[2 * nn][1] = r2;
                bv[2 * nn + 1][0] = r1; bv[2 * nn + 1][1] = r3;
            }
#pragma unroll
            for (int mi = 0; mi < 2; mi++) {
                uint32_t pa0 = packh2(S[mi][2 * kk][0],     S[mi][2 * kk][1]);
                uint32_t pa1 = packh2(S[mi][2 * kk][2],     S[mi][2 * kk][3]);
                uint32_t pa2 = packh2(S[mi][2 * kk + 1][0], S[mi][2 * kk + 1][1]);
                uint32_t pa3 = packh2(S[mi][2 * kk + 1][2], S[mi][2 * kk + 1][3]);
#pragma unroll
                for (int nt = 0; nt < 4; nt++)
                    mmah(O[mi][nt], pa0, pa1, pa2, pa3, bv[nt][0], bv[nt][1]);
            }
        }
    }

    // ---- row-sum reduce over quad lanes ----
#pragma unroll
    for (int mi = 0; mi < 2; mi++)
#pragma unroll
        for (int r = 0; r < 2; r++) {
            rs[mi][r] += __shfl_xor_sync(0xFFFFFFFFu, rs[mi][r], 1);
            rs[mi][r] += __shfl_xor_sync(0xFFFFFFFFu, rs[mi][r], 2);
        }

    // ---- normalize + fp16 write ----
    const int tq = lid & 3, g = lid >> 2;
    const int c0 = head * 32;
#pragma unroll
    for (int mi = 0; mi < 2; mi++) {
        const float i0 = 1.0f / rs[mi][0];
        const float i1 = 1.0f / rs[mi][1];
        const int tok0 = win * 64 + mhalf * 32 + mi * 16 + g;
        __half* r0p = attns + ((size_t)b * NPIX + tok0) * CC + c0;
        __half* r8p = r0p + 8 * CC;
#pragma unroll
        for (int nt = 0; nt < 4; nt++) {
            const int d = nt * 8 + 2 * tq;
            *(uint32_t*)(r0p + d) = packh2(O[mi][nt][0] * i0, O[mi][nt][1] * i0);
            *(uint32_t*)(r8p + d) = packh2(O[mi][nt][2] * i1, O[mi][nt][3] * i1);
        }
    }
}

// ---------------------------------------------------------------------------
extern "C" void kernel_launch(void* const* d_in, const int* in_sizes, int n_in,
                              void* d_out, int out_size)
{
    (void)in_sizes; (void)n_in; (void)out_size;
    const float* x      = (const float*)d_in[0];
    const float* w_qkv  = (const float*)d_in[1];
    const float* w_proj = (const float*)d_in[2];
    const int*   shift  = (const int*)d_in[3];

    __half *qkv, *xs, *as, *wqs, *wps;
    cudaGetSymbolAddress((void**)&qkv, g_qkv);
    cudaGetSymbolAddress((void**)&xs,  g_xs);
    cudaGetSymbolAddress((void**)&as,  g_as);
    cudaGetSymbolAddress((void**)&wqs, g_wqs);
    cudaGetSymbolAddress((void**)&wps, g_wps);

    cudaFuncSetAttribute(gemm_fp16, cudaFuncAttributeMaxDynamicSharedMemorySize, DYN_SMEM);
    cudaFuncSetAttribute(attn_kernel, cudaFuncAttributeMaxDynamicSharedMemorySize, ATTN_SMEM);

    convert_w2<<<1024, 256>>>(w_qkv, w_proj, wqs, wps);
    convert_x<<<dim3(128, 8, 16), 256>>>(x, xs, shift);

    // K1: qkv = W @ X, fp16 out (permuted pixel space)
    gemm_fp16<<<dim3(32, 6, 16), 256, DYN_SMEM>>>(wqs, xs, qkv, C3, shift, 0, 1);

    attn_kernel<<<dim3(2, 64, 16), 256, ATTN_SMEM>>>(qkv, as);

    // K3: out = W_proj @ attn, fp32 out, un-permute epilogue
    gemm_fp16<<<dim3(32, 2, 16), 256, DYN_SMEM>>>(wps, as, d_out, CC, shift, 1, 0);
}

// round 17
// speedup vs baseline: 1.0733x; 1.0052x over previous
#include <cuda_runtime.h>
#include <cuda_bf16.h>
#include <cuda_fp16.h>
#include <stdint.h>

#define CC 256
#define C3 768
#define NPIX 4096
#define BATCH 16
#define NHEAD 8
#define NCH 4                 // 4 k-chunks of 64
#define PITCH 144             // 128B chunk-row + 16B pad
#define TILE (128 * PITCH)       // 18432 per operand
#define STAGE (2 * TILE)         // 36864
#define NSTAGE 3
#define DYN_SMEM (NSTAGE * STAGE) // 110592 -> 2 CTAs/SM

// attention smem: per head q,k,v 32 rows x 144B; 4 heads; double-buffered (2 windows)
#define AH_T 4608
#define AH_BYTES (3 * AH_T)          // 13824
#define AW_BYTES (4 * AH_BYTES)      // 55296 per window
#define ATTN_SMEM (2 * AW_BYTES)     // 110592 -> 2 blocks/SM

// ---------------- scratch -----------------------------------------------
__device__ __align__(16) __half g_qkv[(size_t)BATCH * C3 * NPIX];
__device__ __align__(16) __half g_xs [(size_t)BATCH * NPIX * CC];
__device__ __align__(16) __half g_as [(size_t)BATCH * NPIX * CC];
__device__ __align__(16) __half g_wqs[(size_t)C3 * CC];
__device__ __align__(16) __half g_wps[(size_t)CC * CC];

// ---------------- helpers -------------------------------------------------
__device__ __forceinline__ uint32_t smem_u32(const void* p) {
    uint32_t a;
    asm("{ .reg .u64 t; cvta.to.shared.u64 t, %1; cvt.u32.u64 %0, t; }" : "=r"(a) : "l"(p));
    return a;
}
__device__ __forceinline__ void cp16(uint32_t d, const void* s) {
    asm volatile("cp.async.cg.shared.global [%0], [%1], 16;" :: "r"(d), "l"(s) : "memory");
}
__device__ __forceinline__ void cp_commit() {
    asm volatile("cp.async.commit_group;" ::: "memory");
}
template <int N> __device__ __forceinline__ void cp_wait() {
    asm volatile("cp.async.wait_group %0;" :: "n"(N) : "memory");
}
__device__ __forceinline__ void ldsm4(uint32_t& r0, uint32_t& r1, uint32_t& r2, uint32_t& r3,
                                      uint32_t addr) {
    asm volatile("ldmatrix.sync.aligned.m8n8.x4.shared.b16 {%0,%1,%2,%3}, [%4];"
                 : "=r"(r0), "=r"(r1), "=r"(r2), "=r"(r3) : "r"(addr));
}
__device__ __forceinline__ void ldsm4t(uint32_t& r0, uint32_t& r1, uint32_t& r2, uint32_t& r3,
                                       uint32_t addr) {
    asm volatile("ldmatrix.sync.aligned.m8n8.x4.trans.shared.b16 {%0,%1,%2,%3}, [%4];"
                 : "=r"(r0), "=r"(r1), "=r"(r2), "=r"(r3) : "r"(addr));
}
__device__ __forceinline__ void mmah(float* d,
                                     uint32_t a0, uint32_t a1, uint32_t a2, uint32_t a3,
                                     uint32_t b0, uint32_t b1) {
    asm volatile(
        "mma.sync.aligned.m16n8k16.row.col.f32.f16.f16.f32 "
        "{%0,%1,%2,%3}, {%4,%5,%6,%7}, {%8,%9}, {%0,%1,%2,%3};"
        : "+f"(d[0]), "+f"(d[1]), "+f"(d[2]), "+f"(d[3])
        : "r"(a0), "r"(a1), "r"(a2), "r"(a3), "r"(b0), "r"(b1));
}
__device__ __forceinline__ uint32_t packh2(float a, float b) {
    __half2 t = __floats2half2_rn(a, b);
    return *(uint32_t*)&t;
}

// ---------------------------------------------------------------------------
// Single-fp16 GEMM (round-14 exact): 128M x 128N CTA, 256 thr (2m x 4n of
// 64x32), 3-stage cp.async, 2 CTAs/SM, commit-every-iteration race fix.
// grid = (32, Mtot/128, 16)
// ---------------------------------------------------------------------------
__global__ __launch_bounds__(256, 2)
void gemm_fp16(const __half* __restrict__ A,
               const __half* __restrict__ Bm,
               void* __restrict__ Dv, int Mtot,
               const int* __restrict__ shift_ptr, int permute, int out_half)
{
    extern __shared__ __align__(16) char dsm[];

    const int tid = threadIdx.x;
    const int wid = tid >> 5;
    const int lid = tid & 31;
    const int bn = blockIdx.x, bm = blockIdx.y, b = blockIdx.z;

    const int warp_m = wid & 1;
    const int warp_n = wid >> 1;
    const uint32_t gq = lid >> 2, tq = lid & 3;

    const uint32_t sbase = smem_u32(dsm);

    const int r = tid >> 1, h = tid & 1;
    const char* Ag = (const char*)A + (size_t)(bm * 128 + r) * 512 + (size_t)h * 64;
    const char* Bg = (const char*)Bm
        + ((size_t)b * NPIX + (size_t)bn * 128 + (size_t)r) * 512 + (size_t)h * 64;
    const uint32_t srow = (uint32_t)r * PITCH + (uint32_t)h * 64;

    auto fill = [&](int c, int s) {
        const uint32_t sa = sbase + (uint32_t)s * STAGE + srow;
        const uint32_t sb = sa + TILE;
        const char* ag = Ag + (size_t)c * 128;
        const char* bg = Bg + (size_t)c * 128;
#pragma unroll
        for (int j = 0; j < 4; j++) cp16(sa + j * 16, ag + j * 16);
#pragma unroll
        for (int j = 0; j < 4; j++) cp16(sb + j * 16, bg + j * 16);
        cp_commit();
    };

    fill(0, 0);
    fill(1, 1);
    fill(2, 2);

    float acc[4][4][4];
#pragma unroll
    for (int mi = 0; mi < 4; mi++)
#pragma unroll
        for (int ni = 0; ni < 4; ni++)
#pragma unroll
            for (int e = 0; e < 4; e++) acc[mi][ni][e] = 0.0f;

    const uint32_t lr = lid & 15, lh = lid >> 4;
    const uint32_t pAr = (uint32_t)(warp_m * 64 + lr) * PITCH + lh * 16u;
    const uint32_t pBr = (uint32_t)(warp_n * 32 + lr) * PITCH + lh * 16u;

    for (int c = 0; c < NCH; c++) {
        cp_wait<NSTAGE - 1>();
        __syncthreads();
        const uint32_t so = sbase + (uint32_t)(c % NSTAGE) * STAGE;
        const uint32_t pA = so + pAr;
        const uint32_t pB = so + TILE + pBr;

#pragma unroll
        for (int ks = 0; ks < 4; ks++) {
            const uint32_t ko = 32u * ks;
            uint32_t bfr[4][2];
#pragma unroll
            for (int j = 0; j < 2; j++) {
                uint32_t r0, r1, r2, r3;
                ldsm4(r0, r1, r2, r3, pB + (uint32_t)j * (16 * PITCH) + ko);
                bfr[2 * j][0] = r0;     bfr[2 * j][1] = r2;
                bfr[2 * j + 1][0] = r1; bfr[2 * j + 1][1] = r3;
            }
            uint32_t af[4][4];
#pragma unroll
            for (int mi = 0; mi < 4; mi++)
                ldsm4(af[mi][0], af[mi][1], af[mi][2], af[mi][3],
                      pA + (uint32_t)mi * (16 * PITCH) + ko);
#pragma unroll
            for (int mi = 0; mi < 4; mi++)
#pragma unroll
                for (int ni = 0; ni < 4; ni++)
                    mmah(acc[mi][ni], af[mi][0], af[mi][1], af[mi][2], af[mi][3],
                         bfr[ni][0], bfr[ni][1]);
        }
        __syncthreads();
        if (c + NSTAGE < NCH) fill(c + NSTAGE, c % NSTAGE);
        else                  cp_commit();     // empty group: keep wait math exact
    }

    const int row_base = bm * 128 + warp_m * 64 + (int)gq;
    const int col_base = bn * 128 + warp_n * 32 + 2 * (int)tq;

    if (out_half) {
        __half* Dh = (__half*)Dv + (size_t)b * Mtot * NPIX;
#pragma unroll
        for (int mi = 0; mi < 4; mi++) {
            const int r0 = row_base + mi * 16;
#pragma unroll
            for (int ni = 0; ni < 4; ni++) {
                const int cl = col_base + ni * 8;
                *(uint32_t*)(Dh + (size_t)r0 * NPIX + cl) =
                    packh2(acc[mi][ni][0], acc[mi][ni][1]);
                *(uint32_t*)(Dh + (size_t)(r0 + 8) * NPIX + cl) =
                    packh2(acc[mi][ni][2], acc[mi][ni][3]);
            }
        }
    } else {
        const int sft = (permute && (*shift_ptr != 0)) ? 4 : 0;
        float* Db = (float*)Dv + (size_t)b * Mtot * NPIX;
#pragma unroll
        for (int mi = 0; mi < 4; mi++) {
            const int r0 = row_base + mi * 16;
#pragma unroll
            for (int ni = 0; ni < 4; ni++) {
                int cl = col_base + ni * 8;
                int col;
                if (permute) {
                    const int win = cl >> 6, tok = cl & 63;
                    const int gh = (((win >> 3) << 3) + (tok >> 3) + sft) & 63;
                    const int gw = (((win & 7) << 3) + (tok & 7) + sft) & 63;
                    col = gh * 64 + gw;
                } else {
                    col = cl;
                }
                *(float2*)(Db + (size_t)r0 * NPIX + col) =
                    make_float2(acc[mi][ni][0], acc[mi][ni][1]);
                *(float2*)(Db + (size_t)(r0 + 8) * NPIX + col) =
                    make_float2(acc[mi][ni][2], acc[mi][ni][3]);
            }
        }
    }
}

// ---------------------------------------------------------------------------
// Merged weight convert: w_qkv (Q rows scaled) then w_proj. 1024 x 256.
// ---------------------------------------------------------------------------
__global__ void convert_w2(const float* __restrict__ Wq, const float* __restrict__ Wp,
                           __half* __restrict__ Wqs, __half* __restrict__ Wps)
{
    int id = blockIdx.x * 256 + threadIdx.x;
    if (id < C3 * 256) {
        float v = Wq[id];
        if ((id >> 8) < CC) v *= 0.17677669529663688f;   // 1/sqrt(32) into Q rows
        Wqs[id] = __float2half(v);
    } else {
        int j = id - C3 * 256;
        Wps[j] = __float2half(Wp[j]);
    }
}

__global__ __launch_bounds__(256) void convert_x(const float* __restrict__ X,
                                                 __half* __restrict__ Xs,
                                                 const int* __restrict__ shift_ptr)
{
    __shared__ float s[32][33];
    const int p0 = blockIdx.x * 32, k0 = blockIdx.y * 32, b = blockIdx.z;
    const int tx = threadIdx.x & 31, ty = threadIdx.x >> 5;
    const int sft = (*shift_ptr != 0) ? 4 : 0;
    const float* xb = X + ((size_t)b * CC + k0) * NPIX + p0;
#pragma unroll
    for (int kk = ty; kk < 32; kk += 8) s[kk][tx] = xb[(size_t)kk * NPIX + tx];
    __syncthreads();
#pragma unroll
    for (int pp = ty; pp < 32; pp += 8) {
        const int p = p0 + pp;
        const int gh = p >> 6, gw = p & 63;
        const int hp = (gh - sft) & 63, wp = (gw - sft) & 63;
        const int pprime = (((hp >> 3) << 3) + (wp >> 3)) * 64 + ((hp & 7) << 3) + (wp & 7);
        Xs[((size_t)b * NPIX + pprime) * CC + k0 + tx] = __float2half(s[tx][pp]);
    }
}

// ---------------------------------------------------------------------------
// HMMA windowed attention v3: 2 warps per (head, window-slot), 2 WINDOWS per
// block with double-buffered smem. Both windows' qkv prefetched via cp.async
// before compute; window-1 loads overlap window-0 compute + epilogue.
// grid = (2 head-groups, 32 window-pairs, 16 batch), block 256.
// ---------------------------------------------------------------------------
__global__ __launch_bounds__(256) void attn_kernel(
    const __half* __restrict__ qkv, __half* __restrict__ attns)
{
    extern __shared__ __align__(16) char smema[];
    const int tid = threadIdx.x;
    const int lid = tid & 31, wid = tid >> 5;
    const int hslot = wid >> 1;          // 0..3
    const int mhalf = wid & 1;           // q-token half (also load role)
    const int head = blockIdx.x * 4 + hslot;
    const int win0 = blockIdx.y * 2, b = blockIdx.z;

    const uint32_t sb0 = smem_u32(smema);

    // ---- prefetch both windows (one commit group each) ----
#pragma unroll
    for (int w = 0; w < 2; w++) {
        const uint32_t hb = sb0 + (uint32_t)w * AW_BYTES + (uint32_t)hslot * AH_BYTES;
        const size_t base = (size_t)b * C3 * NPIX + (size_t)(head * 32 + lid) * NPIX
                          + (size_t)(win0 + w) * 64;
        const uint32_t dr = (uint32_t)lid * 144u;
        if (mhalf == 0) {
            const char* gq = (const char*)(qkv + base);
            const char* gk = (const char*)(qkv + base + (size_t)CC * NPIX);
#pragma unroll
            for (int j = 0; j < 8; j++) {
                cp16(hb + dr + j * 16, gq + j * 16);
                cp16(hb + AH_T + dr + j * 16, gk + j * 16);
            }
        } else {
            const char* gv = (const char*)(qkv + base + (size_t)(2 * CC) * NPIX);
#pragma unroll
            for (int j = 0; j < 8; j++)
                cp16(hb + 2 * AH_T + dr + j * 16, gv + j * 16);
        }
        cp_commit();
    }

    const uint32_t tr  = (uint32_t)((lid & 7) + ((lid & 16) >> 1));
    const uint32_t tcb = (uint32_t)(lid & 8) * 2u;
    const uint32_t vr  = (uint32_t)(lid & 15);
    const uint32_t vh16 = (uint32_t)(lid >> 4) * 16u;
    const uint32_t mq = (uint32_t)(mhalf * 64);
    const int tq = lid & 3, g = lid >> 2;
    const int c0 = head * 32;

#pragma unroll 1
    for (int w = 0; w < 2; w++) {
        if (w == 0) cp_wait<1>(); else cp_wait<0>();
        __syncthreads();
        const uint32_t hb = sb0 + (uint32_t)w * AW_BYTES + (uint32_t)hslot * AH_BYTES;
        const uint32_t qsm = hb, ksm = hb + AH_T, vsm = hb + 2 * AH_T;

        float O[2][4][4];
        float rs[2][2];
#pragma unroll
        for (int mi = 0; mi < 2; mi++) {
            rs[mi][0] = 0.0f; rs[mi][1] = 0.0f;
#pragma unroll
            for (int nt = 0; nt < 4; nt++)
#pragma unroll
                for (int e = 0; e < 4; e++) O[mi][nt][e] = 0.0f;
        }

#pragma unroll 1
        for (int half = 0; half < 2; half++) {     // key halves
            float S[2][4][4];
#pragma unroll
            for (int mi = 0; mi < 2; mi++)
#pragma unroll
                for (int nj = 0; nj < 4; nj++)
#pragma unroll
                    for (int e = 0; e < 4; e++) S[mi][nj][e] = 0.0f;

            // ---- S = Q.K^T ----
#pragma unroll
            for (int kk = 0; kk < 2; kk++) {
                uint32_t af[2][4];
#pragma unroll
                for (int mi = 0; mi < 2; mi++)
                    ldsm4t(af[mi][0], af[mi][1], af[mi][2], af[mi][3],
                           qsm + ((uint32_t)kk * 16u + tr) * 144u
                               + mq + (uint32_t)(mi * 32) + tcb);
                uint32_t bf2[4][2];
#pragma unroll
                for (int jj = 0; jj < 2; jj++) {
                    uint32_t r0, r1, r2, r3;
                    ldsm4t(r0, r1, r2, r3,
                           ksm + ((uint32_t)kk * 16u + tr) * 144u
                               + (uint32_t)(half * 64 + jj * 32) + tcb);
                    bf2[2 * jj][0] = r0;     bf2[2 * jj][1] = r2;
                    bf2[2 * jj + 1][0] = r1; bf2[2 * jj + 1][1] = r3;
                }
#pragma unroll
                for (int mi = 0; mi < 2; mi++)
#pragma unroll
                    for (int nj = 0; nj < 4; nj++)
                        mmah(S[mi][nj], af[mi][0], af[mi][1], af[mi][2], af[mi][3],
                             bf2[nj][0], bf2[nj][1]);
            }

            // ---- exp + partial row sums ----
#pragma unroll
            for (int mi = 0; mi < 2; mi++)
#pragma unroll
                for (int nj = 0; nj < 4; nj++) {
                    S[mi][nj][0] = __expf(S[mi][nj][0]);
                    S[mi][nj][1] = __expf(S[mi][nj][1]);
                    S[mi][nj][2] = __expf(S[mi][nj][2]);
                    S[mi][nj][3] = __expf(S[mi][nj][3]);
                    rs[mi][0] += S[mi][nj][0] + S[mi][nj][1];
                    rs[mi][1] += S[mi][nj][2] + S[mi][nj][3];
                }

            // ---- O += P.V ----
#pragma unroll
            for (int kk = 0; kk < 2; kk++) {
                uint32_t bv[4][2];
                const uint32_t kcb = (uint32_t)(half * 64 + kk * 32) + vh16;
#pragma unroll
                for (int nn = 0; nn < 2; nn++) {
                    uint32_t r0, r1, r2, r3;
                    ldsm4(r0, r1, r2, r3, vsm + ((uint32_t)(nn * 16) + vr) * 144u + kcb);
                    bv[2 * nn][0] = r0;     bv[2 * nn][1] = r2;
                    bv[2 * nn + 1][0] = r1; bv[2 * nn + 1][1] = r3;
                }
#pragma unroll
                for (int mi = 0; mi < 2; mi++) {
                    uint32_t pa0 = packh2(S[mi][2 * kk][0],     S[mi][2 * kk][1]);
                    uint32_t pa1 = packh2(S[mi][2 * kk][2],     S[mi][2 * kk][3]);
                    uint32_t pa2 = packh2(S[mi][2 * kk + 1][0], S[mi][2 * kk + 1][1]);
                    uint32_t pa3 = packh2(S[mi][2 * kk + 1][2], S[mi][2 * kk + 1][3]);
#pragma unroll
                    for (int nt = 0; nt < 4; nt++)
                        mmah(O[mi][nt], pa0, pa1, pa2, pa3, bv[nt][0], bv[nt][1]);
                }
            }
        }

        // ---- row-sum reduce over quad lanes ----
#pragma unroll
        for (int mi = 0; mi < 2; mi++)
#pragma unroll
            for (int r = 0; r < 2; r++) {
                rs[mi][r] += __shfl_xor_sync(0xFFFFFFFFu, rs[mi][r], 1);
                rs[mi][r] += __shfl_xor_sync(0xFFFFFFFFu, rs[mi][r], 2);
            }

        // ---- normalize + fp16 write (overlaps window-1 loads) ----
#pragma unroll
        for (int mi = 0; mi < 2; mi++) {
            const float i0 = 1.0f / rs[mi][0];
            const float i1 = 1.0f / rs[mi][1];
            const int tok0 = (win0 + w) * 64 + mhalf * 32 + mi * 16 + g;
            __half* r0p = attns + ((size_t)b * NPIX + tok0) * CC + c0;
            __half* r8p = r0p + 8 * CC;
#pragma unroll
            for (int nt = 0; nt < 4; nt++) {
                const int d = nt * 8 + 2 * tq;
                *(uint32_t*)(r0p + d) = packh2(O[mi][nt][0] * i0, O[mi][nt][1] * i0);
                *(uint32_t*)(r8p + d) = packh2(O[mi][nt][2] * i1, O[mi][nt][3] * i1);
            }
        }
    }
}

// ---------------------------------------------------------------------------
extern "C" void kernel_launch(void* const* d_in, const int* in_sizes, int n_in,
                              void* d_out, int out_size)
{
    (void)in_sizes; (void)n_in; (void)out_size;
    const float* x      = (const float*)d_in[0];
    const float* w_qkv  = (const float*)d_in[1];
    const float* w_proj = (const float*)d_in[2];
    const int*   shift  = (const int*)d_in[3];

    __half *qkv, *xs, *as, *wqs, *wps;
    cudaGetSymbolAddress((void**)&qkv, g_qkv);
    cudaGetSymbolAddress((void**)&xs,  g_xs);
    cudaGetSymbolAddress((void**)&as,  g_as);
    cudaGetSymbolAddress((void**)&wqs, g_wqs);
    cudaGetSymbolAddress((void**)&wps, g_wps);

    cudaFuncSetAttribute(gemm_fp16, cudaFuncAttributeMaxDynamicSharedMemorySize, DYN_SMEM);
    cudaFuncSetAttribute(attn_kernel, cudaFuncAttributeMaxDynamicSharedMemorySize, ATTN_SMEM);

    convert_w2<<<1024, 256>>>(w_qkv, w_proj, wqs, wps);
    convert_x<<<dim3(128, 8, 16), 256>>>(x, xs, shift);

    // K1: qkv = W @ X, fp16 out (permuted pixel space)
    gemm_fp16<<<dim3(32, 6, 16), 256, DYN_SMEM>>>(wqs, xs, qkv, C3, shift, 0, 1);

    attn_kernel<<<dim3(2, 32, 16), 256, ATTN_SMEM>>>(qkv, as);

    // K3: out = W_proj @ attn, fp32 out, un-permute epilogue
    gemm_fp16<<<dim3(32, 2, 16), 256, DYN_SMEM>>>(wps, as, d_out, CC, shift, 1, 0);
}